// round 5
// baseline (speedup 1.0000x reference)
#include <cuda_runtime.h>

// Apply_Mask v5 — 2 warps per slice (64-thread CTA), 4 front-batched LDG.128
// per lane => ~16 data regs/thread => ~2x occupancy vs v4. Cross-warp
// reduction via 2 tiny __syncthreads. T==0 (half the slices): pure copy,
// no barriers, stores gated only on loads.

#define H 32
#define W 32
#define HW 1024

__global__ void __launch_bounds__(64)
apply_mask_v5(const float* __restrict__ x,
              const int* __restrict__ T,
              const int* __restrict__ drop_block_ptr,
              float* __restrict__ out)
{
    __shared__ unsigned skey[2];
    __shared__ unsigned sidx[2];

    const int tid = threadIdx.x;          // 0..63
    const int warp = tid >> 5;            // 0..1
    const int slice = blockIdx.x;
    const size_t base = (size_t)slice * HW;

    const float4* __restrict__ xin = reinterpret_cast<const float4*>(x + base);
    float4* __restrict__ o = reinterpret_cast<float4*>(out + base);

    // T load first, in flight alongside bulk loads (CTA-uniform value).
    const int t = __ldg(T + slice);

    // ---- front-batched bulk load: 4 x LDG.128 per lane ----
    // float4 index f = j*64 + tid  (covers all 256 float4 of the slice)
    float4 v[4];
#pragma unroll
    for (int j = 0; j < 4; j++)
        v[j] = __ldcs(xin + j * 64 + tid);

    if (t == 0) {
        // ---- copy path: no reduction, no barriers ----
#pragma unroll
        for (int j = 0; j < 4; j++)
            __stcs(o + j * 64 + tid, v[j]);
        return;
    }

    // ---- local max (pairwise tree), then warp REDUX on ordered key ----
    float m01 = fmaxf(fmaxf(fmaxf(v[0].x, v[0].y), fmaxf(v[0].z, v[0].w)),
                      fmaxf(fmaxf(v[1].x, v[1].y), fmaxf(v[1].z, v[1].w)));
    float m23 = fmaxf(fmaxf(fmaxf(v[2].x, v[2].y), fmaxf(v[2].z, v[2].w)),
                      fmaxf(fmaxf(v[3].x, v[3].y), fmaxf(v[3].z, v[3].w)));
    float m = fmaxf(m01, m23);

    unsigned u = __float_as_uint(m);
    unsigned key = u ^ (unsigned)(((int)u >> 31) | 0x80000000);
    key = __reduce_max_sync(0xffffffffu, key);

    if ((tid & 31) == 0) skey[warp] = key;
    __syncthreads();
    key = max(skey[0], skey[1]);

    unsigned mu = key ^ (unsigned)((~((int)key >> 31)) | 0x80000000);
    const float maxf = __uint_as_float(mu);

    // ---- first-occurrence index of maxf ----
    unsigned idx = HW;
    {
        const float* vf = &v[0].x;
#pragma unroll
        for (int j = 0; j < 4; j++) {
#pragma unroll
            for (int i = 0; i < 4; i++) {
                const unsigned e = (unsigned)((j * 64 + tid) * 4 + i);
                if (vf[j * 4 + i] == maxf) idx = min(idx, e);
            }
        }
    }
    idx = __reduce_min_sync(0xffffffffu, idx);

    if ((tid & 31) == 0) sidx[warp] = idx;
    __syncthreads();
    idx = min(sidx[0], sidx[1]);

    // ---- box + lambda ----
    const int mh = (int)(idx >> 5);
    const int mw = (int)(idx & (W - 1));
    const int db = drop_block_ptr ? *drop_block_ptr : 5;
    const int half = db >> 1;

    const int h1 = max(mh - half, 0);
    const int h2 = min(mh + half, H - 1);
    const int w1 = max(mw - half, 0);
    const int w2 = min(mw + half, W - 1);

    const int area = (h2 - h1 + 1) * (w2 - w1 + 1);
    const float lam = (float)HW / (float)(HW - area);

    // element e = (j*64 + tid)*4 + i  ->  row = j*8 + (tid>>3),
    //                                     col = (tid&7)*4 + i
    const int rbase = tid >> 3;
    const int cbase = (tid & 7) * 4;

    bool in_col[4];
#pragma unroll
    for (int i = 0; i < 4; i++)
        in_col[i] = (unsigned)(cbase + i - w1) <= (unsigned)(w2 - w1);

    float row_scale[4];  // scale when in_col true: 0 inside box, lam outside
#pragma unroll
    for (int j = 0; j < 4; j++) {
        const int r = j * 8 + rbase;
        const bool in_row = (unsigned)(r - h1) <= (unsigned)(h2 - h1);
        row_scale[j] = in_row ? 0.0f : lam;
    }

    // ---- scale + store ----
#pragma unroll
    for (int j = 0; j < 4; j++) {
        float4 w4;
        w4.x = v[j].x * (in_col[0] ? row_scale[j] : lam);
        w4.y = v[j].y * (in_col[1] ? row_scale[j] : lam);
        w4.z = v[j].z * (in_col[2] ? row_scale[j] : lam);
        w4.w = v[j].w * (in_col[3] ? row_scale[j] : lam);
        __stcs(o + j * 64 + tid, w4);
    }
}

extern "C" void kernel_launch(void* const* d_in, const int* in_sizes, int n_in,
                              void* d_out, int out_size)
{
    const float* x = (const float*)d_in[0];
    const int* T = (const int*)d_in[1];
    const int* db = (n_in >= 3) ? (const int*)d_in[2] : nullptr;
    float* out = (float*)d_out;

    const int n_slices = in_sizes[0] / HW;  // 32768

    apply_mask_v5<<<n_slices, 64>>>(x, T, db, out);
}